// round 15
// baseline (speedup 1.0000x reference)
#include <cuda_runtime.h>
#include <cuda_bf16.h>
#include <cuda_fp16.h>
#include <math.h>
#include <stdint.h>

#define BB   128
#define LL   1024
#define DK   128
#define DV   256
#define HH   256
#define NN   50
#define MM   (BB * LL)   // 131072 rows

typedef unsigned long long u64;

// ---------------- packed f32x2 helpers ----------------
__device__ __forceinline__ u64 fma2(u64 a, u64 b, u64 c) {
    u64 d; asm("fma.rn.f32x2 %0, %1, %2, %3;" : "=l"(d) : "l"(a), "l"(b), "l"(c)); return d;
}
__device__ __forceinline__ u64 add2(u64 a, u64 b) {
    u64 d; asm("add.rn.f32x2 %0, %1, %2;" : "=l"(d) : "l"(a), "l"(b)); return d;
}
__device__ __forceinline__ u64 pack2(float lo, float hi) {
    u64 r; asm("mov.b64 %0, {%1, %2};" : "=l"(r) : "f"(lo), "f"(hi)); return r;
}
__device__ __forceinline__ float2 unpack2(u64 v) {
    float2 r; asm("mov.b64 {%0, %1}, %2;" : "=f"(r.x), "=f"(r.y) : "l"(v)); return r;
}

// ---------------- fast activations (MUFU-based, ~1e-6 abs error) ----------------
__device__ __forceinline__ float fast_tanh(float x) {
    float t = __expf(2.0f * x);
    return 1.0f - __fdividef(2.0f, t + 1.0f);
}
__device__ __forceinline__ float fast_sigmoid(float x) {
    return __fdividef(1.0f, 1.0f + __expf(-x));
}

// ---------------- async / smem helpers ----------------
__device__ __forceinline__ uint32_t smem_u32(const void* p) {
    uint32_t a;
    asm("{ .reg .u64 t; cvta.to.shared.u64 t, %1; cvt.u32.u64 %0, t; }" : "=r"(a) : "l"(p));
    return a;
}
__device__ __forceinline__ void cpasync16(uint32_t saddr, const void* gptr) {
    asm volatile("cp.async.cg.shared.global [%0], [%1], 16;" :: "r"(saddr), "l"(gptr) : "memory");
}
__device__ __forceinline__ void cpasync8(uint32_t saddr, const void* gptr) {
    asm volatile("cp.async.ca.shared.global [%0], [%1], 8;" :: "r"(saddr), "l"(gptr) : "memory");
}
__device__ __forceinline__ uint32_t lds32(uint32_t addr) {
    uint32_t v; asm volatile("ld.shared.b32 %0, [%1];" : "=r"(v) : "r"(addr)); return v;
}
__device__ __forceinline__ void mma16816(float* c, const uint32_t* a, const uint32_t* b) {
    asm volatile(
        "mma.sync.aligned.m16n8k16.row.col.f32.bf16.bf16.f32 "
        "{%0,%1,%2,%3}, {%4,%5,%6,%7}, {%8,%9}, {%0,%1,%2,%3};"
        : "+f"(c[0]), "+f"(c[1]), "+f"(c[2]), "+f"(c[3])
        : "r"(a[0]), "r"(a[1]), "r"(a[2]), "r"(a[3]), "r"(b[0]), "r"(b[1]));
}

// ------------------------- scratch (device globals; no allocs) -------------------------
__device__ __half         g_e[(size_t)MM * DV];                               // gates as fp16
__device__ __half         g_a[(size_t)MM * DV];
__device__ float          g_score[(size_t)MM * NN];
__device__ __nv_bfloat16  g_ibhi[(size_t)MM * DV];                            // interactions (hi only)
__device__ __nv_bfloat16  g_pbhi[(size_t)MM * DK], g_pblo[(size_t)MM * DK];   // problems
__device__ __nv_bfloat16  g_rhi[(size_t)MM * DV],  g_rlo[(size_t)MM * DV];    // scan reads
__device__ __nv_bfloat16  g_wehi[DV * DV];
__device__ __nv_bfloat16  g_wahi[DV * DV];
__device__ __nv_bfloat16  g_wohi[HH * (DV + DK)], g_wolo[HH * (DV + DK)];
__device__ __nv_bfloat16  g_wkhi[64 * DK], g_wklo[64 * DK];   // w_key padded to 64 rows (rest stays 0)

// =======================================================================================
// f32 -> bf16 conversions
// =======================================================================================
__device__ __forceinline__ void split4(float4 v, ushort4& h, ushort4& l) {
    __nv_bfloat16 b; float f;
    b = __float2bfloat16(v.x); h.x = __bfloat16_as_ushort(b); f = v.x - __bfloat162float(b);
    l.x = __bfloat16_as_ushort(__float2bfloat16(f));
    b = __float2bfloat16(v.y); h.y = __bfloat16_as_ushort(b); f = v.y - __bfloat162float(b);
    l.y = __bfloat16_as_ushort(__float2bfloat16(f));
    b = __float2bfloat16(v.z); h.z = __bfloat16_as_ushort(b); f = v.z - __bfloat162float(b);
    l.z = __bfloat16_as_ushort(__float2bfloat16(f));
    b = __float2bfloat16(v.w); h.w = __bfloat16_as_ushort(b); f = v.w - __bfloat162float(b);
    l.w = __bfloat16_as_ushort(__float2bfloat16(f));
}
__device__ __forceinline__ ushort4 hi4(float4 v) {
    ushort4 h;
    h.x = __bfloat16_as_ushort(__float2bfloat16(v.x));
    h.y = __bfloat16_as_ushort(__float2bfloat16(v.y));
    h.z = __bfloat16_as_ushort(__float2bfloat16(v.z));
    h.w = __bfloat16_as_ushort(__float2bfloat16(v.w));
    return h;
}

__global__ void __launch_bounds__(256) conv_kernel(const float* __restrict__ x,
                                                   __nv_bfloat16* __restrict__ hi,
                                                   __nv_bfloat16* __restrict__ lo,
                                                   int n4)
{
    int i = blockIdx.x * 256 + threadIdx.x;
    if (i >= n4) return;
    ushort4 h, l;
    split4(reinterpret_cast<const float4*>(x)[i], h, l);
    reinterpret_cast<ushort4*>(hi)[i] = h;
    reinterpret_cast<ushort4*>(lo)[i] = l;
}

__global__ void __launch_bounds__(256) conv_hi_kernel(const float* __restrict__ x,
                                                      __nv_bfloat16* __restrict__ hi,
                                                      int n4)
{
    int i = blockIdx.x * 256 + threadIdx.x;
    if (i >= n4) return;
    reinterpret_cast<ushort4*>(hi)[i] = hi4(reinterpret_cast<const float4*>(x)[i]);
}

// Weight conversions: two hi-only (w_erase, w_add) + two hi/lo (w_out, w_key), one launch
__global__ void __launch_bounds__(256) conv_w_kernel(
    const float* __restrict__ x0, __nv_bfloat16* __restrict__ h0, int n0,
    const float* __restrict__ x1, __nv_bfloat16* __restrict__ h1, int n1,
    const float* __restrict__ x2, __nv_bfloat16* __restrict__ h2, __nv_bfloat16* __restrict__ l2, int n2,
    const float* __restrict__ x3, __nv_bfloat16* __restrict__ h3, __nv_bfloat16* __restrict__ l3, int n3)
{
    int i = blockIdx.x * 256 + threadIdx.x;
    int j = i;
    if (j < n0) { reinterpret_cast<ushort4*>(h0)[j] = hi4(reinterpret_cast<const float4*>(x0)[j]); return; }
    j -= n0;
    if (j < n1) { reinterpret_cast<ushort4*>(h1)[j] = hi4(reinterpret_cast<const float4*>(x1)[j]); return; }
    j -= n1;
    const float* x; __nv_bfloat16 *hi, *lo;
    if (j < n2) { x = x2; hi = h2; lo = l2; }
    else { j -= n2; if (j >= n3) return; x = x3; hi = h3; lo = l3; }
    ushort4 h, l;
    split4(reinterpret_cast<const float4*>(x)[j], h, l);
    reinterpret_cast<ushort4*>(hi)[j] = h;
    reinterpret_cast<ushort4*>(lo)[j] = l;
}

// =======================================================================================
// HMMA score GEMM + softmax epilogue (R6-proven, unchanged — stays 3-pass).
// =======================================================================================
#define SMATA 10240u
#define SMATB 5120u
#define SBUF  30720u

__global__ void __launch_bounds__(128)
score_hmma(const __nv_bfloat16* __restrict__ phi, const __nv_bfloat16* __restrict__ plo,
           const __nv_bfloat16* __restrict__ wkhi, const __nv_bfloat16* __restrict__ wklo,
           float* __restrict__ S)
{
    extern __shared__ __align__(16) char dsm[];
    const uint32_t dbase = smem_u32(dsm);

    const int tid = threadIdx.x;
    const int m0 = blockIdx.x * 128;
    const int wid = tid >> 5;
    const int lane = tid & 31;
    const int g  = lane >> 2;
    const int t2 = (lane & 3) * 2;
    const int warpM = wid * 32;

    auto load_chunk = [&](int c) {
        uint32_t sb = dbase + (uint32_t)(c & 1) * SBUF;
        int k0 = c * 32;
#pragma unroll
        for (int i = 0; i < 4; ++i) {
            int idx = tid + 128 * i;
            int row = idx >> 2, seg = idx & 3;
            uint32_t so = (uint32_t)(row * 80 + seg * 16);
            size_t gA = (size_t)(m0 + row) * DK + k0 + seg * 8;
            cpasync16(sb + so,         phi + gA);
            cpasync16(sb + SMATA + so, plo + gA);
        }
#pragma unroll
        for (int i = 0; i < 2; ++i) {
            int idx = tid + 128 * i;
            int row = idx >> 2, seg = idx & 3;
            uint32_t so = (uint32_t)(row * 80 + seg * 16);
            size_t gB = (size_t)row * DK + k0 + seg * 8;
            cpasync16(sb + 2 * SMATA + so,         wkhi + gB);
            cpasync16(sb + 2 * SMATA + SMATB + so, wklo + gB);
        }
        asm volatile("cp.async.commit_group;" ::: "memory");
    };

    float acc[2][8][4];
#pragma unroll
    for (int mt = 0; mt < 2; ++mt)
#pragma unroll
        for (int nt = 0; nt < 8; ++nt)
#pragma unroll
            for (int q = 0; q < 4; ++q) acc[mt][nt][q] = 0.f;

    load_chunk(0);

    for (int c = 0; c < 4; ++c) {
        if (c + 1 < 4) {
            load_chunk(c + 1);
            asm volatile("cp.async.wait_group 1;" ::: "memory");
        } else {
            asm volatile("cp.async.wait_group 0;" ::: "memory");
        }
        __syncthreads();

        uint32_t sb = dbase + (uint32_t)(c & 1) * SBUF;
#pragma unroll
        for (int ks = 0; ks < 2; ++ks) {
            const uint32_t cb = (uint32_t)((ks * 16 + t2) * 2);
            uint32_t a_h[2][4], a_l[2][4];
#pragma unroll
            for (int mt = 0; mt < 2; ++mt) {
                uint32_t r0 = sb + (uint32_t)((warpM + mt * 16 + g) * 80) + cb;
                uint32_t r8 = r0 + 8 * 80;
                a_h[mt][0] = lds32(r0);         a_h[mt][1] = lds32(r8);
                a_h[mt][2] = lds32(r0 + 16);    a_h[mt][3] = lds32(r8 + 16);
                a_l[mt][0] = lds32(r0 + SMATA); a_l[mt][1] = lds32(r8 + SMATA);
                a_l[mt][2] = lds32(r0 + SMATA + 16); a_l[mt][3] = lds32(r8 + SMATA + 16);
            }
            uint32_t b_h[8][2], b_l[8][2];
#pragma unroll
            for (int nt = 0; nt < 8; ++nt) {
                uint32_t rr = sb + 2 * SMATA + (uint32_t)((nt * 8 + g) * 80) + cb;
                b_h[nt][0] = lds32(rr);          b_h[nt][1] = lds32(rr + 16);
                b_l[nt][0] = lds32(rr + SMATB);  b_l[nt][1] = lds32(rr + SMATB + 16);
            }
#pragma unroll
            for (int mt = 0; mt < 2; ++mt)
#pragma unroll
                for (int nt = 0; nt < 8; ++nt) {
                    mma16816(acc[mt][nt], a_h[mt], b_h[nt]);
                    mma16816(acc[mt][nt], a_h[mt], b_l[nt]);
                    mma16816(acc[mt][nt], a_l[mt], b_h[nt]);
                }
        }
        __syncthreads();
    }

#pragma unroll
    for (int mt = 0; mt < 2; ++mt) {
#pragma unroll
        for (int hf = 0; hf < 2; ++hf) {
            int row = m0 + warpM + mt * 16 + g + hf * 8;
            float v[16];
#pragma unroll
            for (int nt = 0; nt < 8; ++nt) {
                int c0 = nt * 8 + t2;
                v[2 * nt]     = (c0     < NN) ? acc[mt][nt][2 * hf]     : -1e30f;
                v[2 * nt + 1] = (c0 + 1 < NN) ? acc[mt][nt][2 * hf + 1] : -1e30f;
            }
            float mx = v[0];
#pragma unroll
            for (int q = 1; q < 16; ++q) mx = fmaxf(mx, v[q]);
            mx = fmaxf(mx, __shfl_xor_sync(0xffffffffu, mx, 1));
            mx = fmaxf(mx, __shfl_xor_sync(0xffffffffu, mx, 2));
            float sum = 0.f;
#pragma unroll
            for (int q = 0; q < 16; ++q) { v[q] = __expf(v[q] - mx); sum += v[q]; }
            sum += __shfl_xor_sync(0xffffffffu, sum, 1);
            sum += __shfl_xor_sync(0xffffffffu, sum, 2);
            float inv = __fdividef(1.f, sum);
            float* op = S + (size_t)row * NN;
#pragma unroll
            for (int nt = 0; nt < 8; ++nt) {
                int c0 = nt * 8 + t2;
                if (c0 < NN)
                    *reinterpret_cast<float2*>(op + c0) =
                        make_float2(v[2 * nt] * inv, v[2 * nt + 1] * inv);
            }
        }
    }
}

// =======================================================================================
// HMMA bf16 GEMM, dual-target (R8-proven config). npass: 1 = ah·bh, 2 = +al·bh, 3 = +ah·bl.
// cfmt: 0 = f32 C stores, 1 = fp16 C stores (gates).
// =======================================================================================
#define MATB 10240u
#define BUFB 40960u

__global__ void __launch_bounds__(256)
gemm_hmma(const __nv_bfloat16* __restrict__ a1hi, const __nv_bfloat16* __restrict__ a1lo,
          int lda1, int k1len,
          const __nv_bfloat16* __restrict__ a2hi, const __nv_bfloat16* __restrict__ a2lo,
          int lda2, int K,
          const __nv_bfloat16* __restrict__ w0hi, const __nv_bfloat16* __restrict__ w0lo,
          const float* __restrict__ b0, void* __restrict__ C0, int act0,
          const __nv_bfloat16* __restrict__ w1hi, const __nv_bfloat16* __restrict__ w1lo,
          const float* __restrict__ b1, void* __restrict__ C1, int act1,
          int nsplit, int npass, int cfmt)
{
    extern __shared__ __align__(16) char dsm[];
    const uint32_t dbase = smem_u32(dsm);

    const int tid = threadIdx.x;
    const int m0 = blockIdx.y * 128;
    const int nb = blockIdx.x;

    const __nv_bfloat16 *whi, *wlo; const float* bias; void* C; int act, nloc;
    if (nb < nsplit) { whi = w0hi; wlo = w0lo; bias = b0; C = C0; act = act0; nloc = nb * 128; }
    else             { whi = w1hi; wlo = w1lo; bias = b1; C = C1; act = act1; nloc = (nb - nsplit) * 128; }

    const int wid = tid >> 5;
    const int lane = tid & 31;
    const int g  = lane >> 2;
    const int t2 = (lane & 3) * 2;
    const int warpM = (wid & 3) * 32;
    const int warpN = (wid >> 2) * 64;

    const int nch = K / 32;

    auto load_chunk = [&](int c) {
        uint32_t sb = dbase + (uint32_t)(c & 1) * BUFB;
        int k0 = c * 32;
        const __nv_bfloat16 *shi, *slo; int ld, kk;
        if (k0 < k1len) { shi = a1hi; slo = a1lo; ld = lda1; kk = k0; }
        else            { shi = a2hi; slo = a2lo; ld = lda2; kk = k0 - k1len; }
#pragma unroll
        for (int i = 0; i < 2; ++i) {
            int gidx = tid + 256 * i;
            int row = gidx >> 2, seg = gidx & 3;
            uint32_t so = (uint32_t)(row * 80 + seg * 16);
            size_t gA = (size_t)(m0 + row) * ld + kk + seg * 8;
            cpasync16(sb + so, shi + gA);
            if (npass >= 2)
                cpasync16(sb + MATB + so, slo + gA);
            size_t gB = (size_t)(nloc + row) * K + k0 + seg * 8;
            cpasync16(sb + 2 * MATB + so, whi + gB);
            if (npass == 3)
                cpasync16(sb + 3 * MATB + so, wlo + gB);
        }
        asm volatile("cp.async.commit_group;" ::: "memory");
    };

    float acc[2][8][4];
#pragma unroll
    for (int mt = 0; mt < 2; ++mt)
#pragma unroll
        for (int nt = 0; nt < 8; ++nt)
#pragma unroll
            for (int q = 0; q < 4; ++q) acc[mt][nt][q] = 0.f;

    load_chunk(0);

    for (int c = 0; c < nch; ++c) {
        if (c + 1 < nch) {
            load_chunk(c + 1);
            asm volatile("cp.async.wait_group 1;" ::: "memory");
        } else {
            asm volatile("cp.async.wait_group 0;" ::: "memory");
        }
        __syncthreads();

        uint32_t sb = dbase + (uint32_t)(c & 1) * BUFB;
#pragma unroll
        for (int ks = 0; ks < 2; ++ks) {
            const uint32_t cb = (uint32_t)((ks * 16 + t2) * 2);
            uint32_t a_h[2][4], a_l[2][4];
#pragma unroll
            for (int mt = 0; mt < 2; ++mt) {
                uint32_t r0 = sb + (uint32_t)((warpM + mt * 16 + g) * 80) + cb;
                uint32_t r8 = r0 + 8 * 80;
                a_h[mt][0] = lds32(r0);        a_h[mt][1] = lds32(r8);
                a_h[mt][2] = lds32(r0 + 16);   a_h[mt][3] = lds32(r8 + 16);
                if (npass >= 2) {
                    a_l[mt][0] = lds32(r0 + MATB); a_l[mt][1] = lds32(r8 + MATB);
                    a_l[mt][2] = lds32(r0 + MATB + 16); a_l[mt][3] = lds32(r8 + MATB + 16);
                }
            }
            uint32_t b_h[8][2];
#pragma unroll
            for (int nt = 0; nt < 8; ++nt) {
                uint32_t rr = sb + 2 * MATB + (uint32_t)((warpN + nt * 8 + g) * 80) + cb;
                b_h[nt][0] = lds32(rr);        b_h[nt][1] = lds32(rr + 16);
            }
            if (npass == 3) {
                uint32_t b_l[8][2];
#pragma unroll
                for (int nt = 0; nt < 8; ++nt) {
                    uint32_t rr = sb + 3 * MATB + (uint32_t)((warpN + nt * 8 + g) * 80) + cb;
                    b_l[nt][0] = lds32(rr);    b_l[nt][1] = lds32(rr + 16);
                }
#pragma unroll
                for (int mt = 0; mt < 2; ++mt)
#pragma unroll
                    for (int nt = 0; nt < 8; ++nt) {
                        mma16816(acc[mt][nt], a_h[mt], b_h[nt]);
                        mma16816(acc[mt][nt], a_h[mt], b_l[nt]);
                        mma16816(acc[mt][nt], a_l[mt], b_h[nt]);
                    }
            } else if (npass == 2) {
#pragma unroll
                for (int mt = 0; mt < 2; ++mt)
#pragma unroll
                    for (int nt = 0; nt < 8; ++nt) {
                        mma16816(acc[mt][nt], a_h[mt], b_h[nt]);
                        mma16816(acc[mt][nt], a_l[mt], b_h[nt]);
                    }
            } else {
#pragma unroll
                for (int mt = 0; mt < 2; ++mt)
#pragma unroll
                    for (int nt = 0; nt < 8; ++nt)
                        mma16816(acc[mt][nt], a_h[mt], b_h[nt]);
            }
        }
        __syncthreads();
    }

#pragma unroll
    for (int mt = 0; mt < 2; ++mt) {
        int r0 = m0 + warpM + mt * 16 + g;
#pragma unroll
        for (int nt = 0; nt < 8; ++nt) {
            int cc = nloc + warpN + nt * 8 + t2;
            float bb0 = bias[cc], bb1 = bias[cc + 1];
            float v0 = acc[mt][nt][0] + bb0, v1 = acc[mt][nt][1] + bb1;
            float v2 = acc[mt][nt][2] + bb0, v3 = acc[mt][nt][3] + bb1;
            if (act == 0) {
                v0 = fast_sigmoid(v0); v1 = fast_sigmoid(v1);
                v2 = fast_sigmoid(v2); v3 = fast_sigmoid(v3);
            } else {
                v0 = fast_tanh(v0); v1 = fast_tanh(v1);
                v2 = fast_tanh(v2); v3 = fast_tanh(v3);
            }
            if (cfmt) {
                __half* Ch = (__half*)C;
                *reinterpret_cast<__half2*>(&Ch[(size_t)r0 * 256 + cc])       = __floats2half2_rn(v0, v1);
                *reinterpret_cast<__half2*>(&Ch[(size_t)(r0 + 8) * 256 + cc]) = __floats2half2_rn(v2, v3);
            } else {
                float* Cf = (float*)C;
                *reinterpret_cast<float2*>(&Cf[(size_t)r0 * 256 + cc])       = make_float2(v0, v1);
                *reinterpret_cast<float2*>(&Cf[(size_t)(r0 + 8) * 256 + cc]) = make_float2(v2, v3);
            }
        }
    }
}

// =======================================================================================
// Scan, warp-autonomous (R8-proven); e/a inputs are fp16.
// =======================================================================================
__global__ void __launch_bounds__(256) scan_kernel(const float* __restrict__ S,
                                                   const __half* __restrict__ E,
                                                   const __half* __restrict__ A,
                                                   const float* __restrict__ M0,
                                                   __nv_bfloat16* __restrict__ Rhi,
                                                   __nv_bfloat16* __restrict__ Rlo)
{
    const int b = blockIdx.x;
    const int d = threadIdx.x;
    const int w = d >> 5;
    const int lane = d & 31;
    __shared__ __align__(16) float ring[8][16][52];

    u64 m[25];
#pragma unroll
    for (int j = 0; j < 25; ++j)
        m[j] = pack2(M0[(2 * j) * DV + d], M0[(2 * j + 1) * DV + d]);

    const float* sp = S + (size_t)b * LL * NN;
    const __half* ep = E + (size_t)b * LL * DV + d;
    const __half* ap = A + (size_t)b * LL * DV + d;
    __nv_bfloat16* rh = Rhi + (size_t)b * LL * DV + d;
    __nv_bfloat16* rl = Rlo + (size_t)b * LL * DV + d;

    auto fetch_slot = [&](int slot, int l) {
        if (lane < 25)
            cpasync8(smem_u32(&ring[w][slot][lane * 2]), sp + (size_t)l * NN + lane * 2);
    };

#pragma unroll
    for (int st = 0; st < 4; ++st) fetch_slot(st, st);
    asm volatile("cp.async.commit_group;" ::: "memory");
#pragma unroll
    for (int st = 0; st < 4; ++st) fetch_slot(4 + st, 4 + st);
    asm volatile("cp.async.commit_group;" ::: "memory");
    asm volatile("cp.async.wait_group 1;" ::: "memory");

    float ecur[4], acur[4], enx[4], anx[4];
#pragma unroll
    for (int st = 0; st < 4; ++st) { ecur[st] = __half2float(ep[(size_t)st * DV]); acur[st] = __half2float(ap[(size_t)st * DV]); }
#pragma unroll
    for (int st = 0; st < 4; ++st) { enx[st] = __half2float(ep[(size_t)(4 + st) * DV]); anx[st] = __half2float(ap[(size_t)(4 + st) * DV]); }
    __syncwarp();

    for (int gi = 0; gi < LL / 4; ++gi) {
        const int base = gi * 4;
#pragma unroll
        for (int st = 0; st < 4; ++st) {
            int ll = base + 8 + st; if (ll > LL - 1) ll = LL - 1;
            fetch_slot((base + 8 + st) & 15, ll);
        }
        asm volatile("cp.async.commit_group;" ::: "memory");
        float etmp[4], atmp[4];
#pragma unroll
        for (int st = 0; st < 4; ++st) {
            int ll = base + 8 + st; if (ll > LL - 1) ll = LL - 1;
            etmp[st] = __half2float(ep[(size_t)ll * DV]);
            atmp[st] = __half2float(ap[(size_t)ll * DV]);
        }

#pragma unroll
        for (int st = 0; st < 4; ++st) {
            const int l = base + st;
            u64 apk  = pack2(acur[st], acur[st]);
            u64 nepk = pack2(-ecur[st], -ecur[st]);
            u64 r0 = 0ull, r1 = 0ull;
            const u64* sb = reinterpret_cast<const u64*>(ring[w][l & 15]);
#pragma unroll
            for (int j = 0; j < 25; ++j) {
                u64 spk = sb[j];
                if (j & 1) r1 = fma2(spk, m[j], r1);
                else       r0 = fma2(spk, m[j], r0);
                u64 tt = fma2(nepk, m[j], apk);
                m[j] = fma2(spk, tt, m[j]);
            }
            float2 rv = unpack2(add2(r0, r1));
            float rr = rv.x + rv.y;
            __nv_bfloat16 h  = __float2bfloat16(rr);
            __nv_bfloat16 lo = __float2bfloat16(rr - __bfloat162float(h));
            rh[(size_t)l * DV] = h;
            rl[(size_t)l * DV] = lo;
        }

        asm volatile("cp.async.wait_group 1;" ::: "memory");
        __syncwarp();
#pragma unroll
        for (int st = 0; st < 4; ++st) {
            ecur[st] = enx[st]; acur[st] = anx[st];
            enx[st] = etmp[st]; anx[st] = atmp[st];
        }
    }
}

// =======================================================================================
// Launch
// =======================================================================================
extern "C" void kernel_launch(void* const* d_in, const int* in_sizes, int n_in,
                              void* d_out, int out_size)
{
    const float* problems     = (const float*)d_in[0];
    const float* interactions = (const float*)d_in[1];
    const float* w_key        = (const float*)d_in[2];
    const float* w_erase_w    = (const float*)d_in[3];
    const float* w_erase_b    = (const float*)d_in[4];
    const float* w_add_w      = (const float*)d_in[5];
    const float* w_add_b      = (const float*)d_in[6];
    const float* w_out_w      = (const float*)d_in[7];
    const float* w_out_b      = (const float*)d_in[8];
    const float* init_memory  = (const float*)d_in[9];
    float* out = (float*)d_out;

    __half *ge, *ga; float *gs;
    __nv_bfloat16 *ibhi, *pbhi, *pblo, *rhi, *rlo;
    __nv_bfloat16 *wehi, *wahi, *wohi, *wolo, *wkhi, *wklo;
    cudaGetSymbolAddress((void**)&ge,   g_e);
    cudaGetSymbolAddress((void**)&ga,   g_a);
    cudaGetSymbolAddress((void**)&gs,   g_score);
    cudaGetSymbolAddress((void**)&ibhi, g_ibhi);
    cudaGetSymbolAddress((void**)&pbhi, g_pbhi);  cudaGetSymbolAddress((void**)&pblo, g_pblo);
    cudaGetSymbolAddress((void**)&rhi,  g_rhi);   cudaGetSymbolAddress((void**)&rlo,  g_rlo);
    cudaGetSymbolAddress((void**)&wehi, g_wehi);
    cudaGetSymbolAddress((void**)&wahi, g_wahi);
    cudaGetSymbolAddress((void**)&wohi, g_wohi);  cudaGetSymbolAddress((void**)&wolo, g_wolo);
    cudaGetSymbolAddress((void**)&wkhi, g_wkhi);  cudaGetSymbolAddress((void**)&wklo, g_wklo);

    cudaFuncSetAttribute(gemm_hmma, cudaFuncAttributeMaxDynamicSharedMemorySize, 2 * BUFB);
    cudaFuncSetAttribute(score_hmma, cudaFuncAttributeMaxDynamicSharedMemorySize, 2 * SBUF);

    // conversions
    conv_hi_kernel<<<(MM * DV / 4 + 255) / 256, 256>>>(interactions, ibhi, MM * DV / 4);
    conv_kernel<<<(MM * DK / 4 + 255) / 256, 256>>>(problems, pbhi, pblo, MM * DK / 4);
    {
        int n0 = DV * DV / 4, n1 = DV * DV / 4, n2 = HH * (DV + DK) / 4, n3 = NN * DK / 4;
        int nt = n0 + n1 + n2 + n3;
        conv_w_kernel<<<(nt + 255) / 256, 256>>>(w_erase_w, wehi, n0,
                                                 w_add_w,   wahi, n1,
                                                 w_out_w,   wohi, wolo, n2,
                                                 w_key,     wkhi, wklo, n3);
    }

    // attention scores (HMMA + softmax epilogue, 3-pass)
    score_hmma<<<MM / 128, 128, 2 * SBUF>>>(pbhi, pblo, wkhi, wklo, gs);

    // merged gate GEMMs — 1-pass pure bf16, fp16 C stores (halves gate DRAM traffic)
    dim3 gg(4, MM / 128);
    gemm_hmma<<<gg, 256, 2 * BUFB>>>(ibhi, ibhi, DV, DV, ibhi, ibhi, DV, DV,
                                     wehi, wehi, w_erase_b, ge, /*sigmoid*/0,
                                     wahi, wahi, w_add_b,   ga, /*tanh*/1, 2, /*npass*/1, /*cfmt*/1);

    // sequential memory scan (warp-autonomous, fp16 gate inputs)
    scan_kernel<<<BB, 256>>>(gs, ge, ga, init_memory, rhi, rlo);

    // output GEMM — 3-pass (REVERTED: 2-pass failed the 1e-3 threshold at 1.66e-3)
    dim3 go(2, MM / 128);
    gemm_hmma<<<go, 256, 2 * BUFB>>>(rhi, rlo, DV, DV, pbhi, pblo, DK, DV + DK,
                                     wohi, wolo, w_out_b, out, /*tanh*/1,
                                     wohi, wolo, w_out_b, out, 1, 2, /*npass*/3, /*cfmt*/0);
}

// round 16
// speedup vs baseline: 1.0209x; 1.0209x over previous
#include <cuda_runtime.h>
#include <cuda_bf16.h>
#include <math.h>
#include <stdint.h>

#define BB   128
#define LL   1024
#define DK   128
#define DV   256
#define HH   256
#define NN   50
#define MM   (BB * LL)   // 131072 rows

typedef unsigned long long u64;

// ---------------- packed f32x2 helpers ----------------
__device__ __forceinline__ u64 fma2(u64 a, u64 b, u64 c) {
    u64 d; asm("fma.rn.f32x2 %0, %1, %2, %3;" : "=l"(d) : "l"(a), "l"(b), "l"(c)); return d;
}
__device__ __forceinline__ u64 add2(u64 a, u64 b) {
    u64 d; asm("add.rn.f32x2 %0, %1, %2;" : "=l"(d) : "l"(a), "l"(b)); return d;
}
__device__ __forceinline__ u64 pack2(float lo, float hi) {
    u64 r; asm("mov.b64 %0, {%1, %2};" : "=l"(r) : "f"(lo), "f"(hi)); return r;
}
__device__ __forceinline__ float2 unpack2(u64 v) {
    float2 r; asm("mov.b64 {%0, %1}, %2;" : "=f"(r.x), "=f"(r.y) : "l"(v)); return r;
}

// ---------------- fast activations (MUFU-based, ~1e-6 abs error) ----------------
__device__ __forceinline__ float fast_tanh(float x) {
    float t = __expf(2.0f * x);
    return 1.0f - __fdividef(2.0f, t + 1.0f);
}
__device__ __forceinline__ float fast_sigmoid(float x) {
    return __fdividef(1.0f, 1.0f + __expf(-x));
}

// ---------------- async / smem helpers ----------------
__device__ __forceinline__ uint32_t smem_u32(const void* p) {
    uint32_t a;
    asm("{ .reg .u64 t; cvta.to.shared.u64 t, %1; cvt.u32.u64 %0, t; }" : "=r"(a) : "l"(p));
    return a;
}
__device__ __forceinline__ void cpasync16(uint32_t saddr, const void* gptr) {
    asm volatile("cp.async.cg.shared.global [%0], [%1], 16;" :: "r"(saddr), "l"(gptr) : "memory");
}
__device__ __forceinline__ void cpasync8(uint32_t saddr, const void* gptr) {
    asm volatile("cp.async.ca.shared.global [%0], [%1], 8;" :: "r"(saddr), "l"(gptr) : "memory");
}
__device__ __forceinline__ uint32_t lds32(uint32_t addr) {
    uint32_t v; asm volatile("ld.shared.b32 %0, [%1];" : "=r"(v) : "r"(addr)); return v;
}
__device__ __forceinline__ void mma16816(float* c, const uint32_t* a, const uint32_t* b) {
    asm volatile(
        "mma.sync.aligned.m16n8k16.row.col.f32.bf16.bf16.f32 "
        "{%0,%1,%2,%3}, {%4,%5,%6,%7}, {%8,%9}, {%0,%1,%2,%3};"
        : "+f"(c[0]), "+f"(c[1]), "+f"(c[2]), "+f"(c[3])
        : "r"(a[0]), "r"(a[1]), "r"(a[2]), "r"(a[3]), "r"(b[0]), "r"(b[1]));
}

// ------------------------- scratch (device globals; no allocs) -------------------------
__device__ float          g_e[(size_t)MM * DV];
__device__ float          g_a[(size_t)MM * DV];
__device__ float          g_score[(size_t)MM * NN];
__device__ __nv_bfloat16  g_ibhi[(size_t)MM * DV];                            // interactions (hi only)
__device__ __nv_bfloat16  g_pbhi[(size_t)MM * DK], g_pblo[(size_t)MM * DK];   // problems
__device__ __nv_bfloat16  g_rhi[(size_t)MM * DV],  g_rlo[(size_t)MM * DV];    // scan reads
__device__ __nv_bfloat16  g_wehi[DV * DV];
__device__ __nv_bfloat16  g_wahi[DV * DV];
__device__ __nv_bfloat16  g_wohi[HH * (DV + DK)], g_wolo[HH * (DV + DK)];
__device__ __nv_bfloat16  g_wkhi[64 * DK], g_wklo[64 * DK];   // w_key padded to 64 rows (rest stays 0)

// =======================================================================================
// f32 -> bf16 conversions
// =======================================================================================
__device__ __forceinline__ void split4(float4 v, ushort4& h, ushort4& l) {
    __nv_bfloat16 b; float f;
    b = __float2bfloat16(v.x); h.x = __bfloat16_as_ushort(b); f = v.x - __bfloat162float(b);
    l.x = __bfloat16_as_ushort(__float2bfloat16(f));
    b = __float2bfloat16(v.y); h.y = __bfloat16_as_ushort(b); f = v.y - __bfloat162float(b);
    l.y = __bfloat16_as_ushort(__float2bfloat16(f));
    b = __float2bfloat16(v.z); h.z = __bfloat16_as_ushort(b); f = v.z - __bfloat162float(b);
    l.z = __bfloat16_as_ushort(__float2bfloat16(f));
    b = __float2bfloat16(v.w); h.w = __bfloat16_as_ushort(b); f = v.w - __bfloat162float(b);
    l.w = __bfloat16_as_ushort(__float2bfloat16(f));
}
__device__ __forceinline__ ushort4 hi4(float4 v) {
    ushort4 h;
    h.x = __bfloat16_as_ushort(__float2bfloat16(v.x));
    h.y = __bfloat16_as_ushort(__float2bfloat16(v.y));
    h.z = __bfloat16_as_ushort(__float2bfloat16(v.z));
    h.w = __bfloat16_as_ushort(__float2bfloat16(v.w));
    return h;
}

__global__ void __launch_bounds__(256) conv_kernel(const float* __restrict__ x,
                                                   __nv_bfloat16* __restrict__ hi,
                                                   __nv_bfloat16* __restrict__ lo,
                                                   int n4)
{
    int i = blockIdx.x * 256 + threadIdx.x;
    if (i >= n4) return;
    ushort4 h, l;
    split4(reinterpret_cast<const float4*>(x)[i], h, l);
    reinterpret_cast<ushort4*>(hi)[i] = h;
    reinterpret_cast<ushort4*>(lo)[i] = l;
}

__global__ void __launch_bounds__(256) conv_hi_kernel(const float* __restrict__ x,
                                                      __nv_bfloat16* __restrict__ hi,
                                                      int n4)
{
    int i = blockIdx.x * 256 + threadIdx.x;
    if (i >= n4) return;
    reinterpret_cast<ushort4*>(hi)[i] = hi4(reinterpret_cast<const float4*>(x)[i]);
}

// Weight conversions: two hi-only (w_erase, w_add) + two hi/lo (w_out, w_key), one launch
__global__ void __launch_bounds__(256) conv_w_kernel(
    const float* __restrict__ x0, __nv_bfloat16* __restrict__ h0, int n0,
    const float* __restrict__ x1, __nv_bfloat16* __restrict__ h1, int n1,
    const float* __restrict__ x2, __nv_bfloat16* __restrict__ h2, __nv_bfloat16* __restrict__ l2, int n2,
    const float* __restrict__ x3, __nv_bfloat16* __restrict__ h3, __nv_bfloat16* __restrict__ l3, int n3)
{
    int i = blockIdx.x * 256 + threadIdx.x;
    int j = i;
    if (j < n0) { reinterpret_cast<ushort4*>(h0)[j] = hi4(reinterpret_cast<const float4*>(x0)[j]); return; }
    j -= n0;
    if (j < n1) { reinterpret_cast<ushort4*>(h1)[j] = hi4(reinterpret_cast<const float4*>(x1)[j]); return; }
    j -= n1;
    const float* x; __nv_bfloat16 *hi, *lo;
    if (j < n2) { x = x2; hi = h2; lo = l2; }
    else { j -= n2; if (j >= n3) return; x = x3; hi = h3; lo = l3; }
    ushort4 h, l;
    split4(reinterpret_cast<const float4*>(x)[j], h, l);
    reinterpret_cast<ushort4*>(hi)[j] = h;
    reinterpret_cast<ushort4*>(l3 == lo ? l3 : lo)[j] = l;
}

// =======================================================================================
// HMMA score GEMM + softmax epilogue (R6-proven, 3-pass).
// =======================================================================================
#define SMATA 10240u
#define SMATB 5120u
#define SBUF  30720u

__global__ void __launch_bounds__(128)
score_hmma(const __nv_bfloat16* __restrict__ phi, const __nv_bfloat16* __restrict__ plo,
           const __nv_bfloat16* __restrict__ wkhi, const __nv_bfloat16* __restrict__ wklo,
           float* __restrict__ S)
{
    extern __shared__ __align__(16) char dsm[];
    const uint32_t dbase = smem_u32(dsm);

    const int tid = threadIdx.x;
    const int m0 = blockIdx.x * 128;
    const int wid = tid >> 5;
    const int lane = tid & 31;
    const int g  = lane >> 2;
    const int t2 = (lane & 3) * 2;
    const int warpM = wid * 32;

    auto load_chunk = [&](int c) {
        uint32_t sb = dbase + (uint32_t)(c & 1) * SBUF;
        int k0 = c * 32;
#pragma unroll
        for (int i = 0; i < 4; ++i) {
            int idx = tid + 128 * i;
            int row = idx >> 2, seg = idx & 3;
            uint32_t so = (uint32_t)(row * 80 + seg * 16);
            size_t gA = (size_t)(m0 + row) * DK + k0 + seg * 8;
            cpasync16(sb + so,         phi + gA);
            cpasync16(sb + SMATA + so, plo + gA);
        }
#pragma unroll
        for (int i = 0; i < 2; ++i) {
            int idx = tid + 128 * i;
            int row = idx >> 2, seg = idx & 3;
            uint32_t so = (uint32_t)(row * 80 + seg * 16);
            size_t gB = (size_t)row * DK + k0 + seg * 8;
            cpasync16(sb + 2 * SMATA + so,         wkhi + gB);
            cpasync16(sb + 2 * SMATA + SMATB + so, wklo + gB);
        }
        asm volatile("cp.async.commit_group;" ::: "memory");
    };

    float acc[2][8][4];
#pragma unroll
    for (int mt = 0; mt < 2; ++mt)
#pragma unroll
        for (int nt = 0; nt < 8; ++nt)
#pragma unroll
            for (int q = 0; q < 4; ++q) acc[mt][nt][q] = 0.f;

    load_chunk(0);

    for (int c = 0; c < 4; ++c) {
        if (c + 1 < 4) {
            load_chunk(c + 1);
            asm volatile("cp.async.wait_group 1;" ::: "memory");
        } else {
            asm volatile("cp.async.wait_group 0;" ::: "memory");
        }
        __syncthreads();

        uint32_t sb = dbase + (uint32_t)(c & 1) * SBUF;
#pragma unroll
        for (int ks = 0; ks < 2; ++ks) {
            const uint32_t cb = (uint32_t)((ks * 16 + t2) * 2);
            uint32_t a_h[2][4], a_l[2][4];
#pragma unroll
            for (int mt = 0; mt < 2; ++mt) {
                uint32_t r0 = sb + (uint32_t)((warpM + mt * 16 + g) * 80) + cb;
                uint32_t r8 = r0 + 8 * 80;
                a_h[mt][0] = lds32(r0);         a_h[mt][1] = lds32(r8);
                a_h[mt][2] = lds32(r0 + 16);    a_h[mt][3] = lds32(r8 + 16);
                a_l[mt][0] = lds32(r0 + SMATA); a_l[mt][1] = lds32(r8 + SMATA);
                a_l[mt][2] = lds32(r0 + SMATA + 16); a_l[mt][3] = lds32(r8 + SMATA + 16);
            }
            uint32_t b_h[8][2], b_l[8][2];
#pragma unroll
            for (int nt = 0; nt < 8; ++nt) {
                uint32_t rr = sb + 2 * SMATA + (uint32_t)((nt * 8 + g) * 80) + cb;
                b_h[nt][0] = lds32(rr);          b_h[nt][1] = lds32(rr + 16);
                b_l[nt][0] = lds32(rr + SMATB);  b_l[nt][1] = lds32(rr + SMATB + 16);
            }
#pragma unroll
            for (int mt = 0; mt < 2; ++mt)
#pragma unroll
                for (int nt = 0; nt < 8; ++nt) {
                    mma16816(acc[mt][nt], a_h[mt], b_h[nt]);
                    mma16816(acc[mt][nt], a_h[mt], b_l[nt]);
                    mma16816(acc[mt][nt], a_l[mt], b_h[nt]);
                }
        }
        __syncthreads();
    }

#pragma unroll
    for (int mt = 0; mt < 2; ++mt) {
#pragma unroll
        for (int hf = 0; hf < 2; ++hf) {
            int row = m0 + warpM + mt * 16 + g + hf * 8;
            float v[16];
#pragma unroll
            for (int nt = 0; nt < 8; ++nt) {
                int c0 = nt * 8 + t2;
                v[2 * nt]     = (c0     < NN) ? acc[mt][nt][2 * hf]     : -1e30f;
                v[2 * nt + 1] = (c0 + 1 < NN) ? acc[mt][nt][2 * hf + 1] : -1e30f;
            }
            float mx = v[0];
#pragma unroll
            for (int q = 1; q < 16; ++q) mx = fmaxf(mx, v[q]);
            mx = fmaxf(mx, __shfl_xor_sync(0xffffffffu, mx, 1));
            mx = fmaxf(mx, __shfl_xor_sync(0xffffffffu, mx, 2));
            float sum = 0.f;
#pragma unroll
            for (int q = 0; q < 16; ++q) { v[q] = __expf(v[q] - mx); sum += v[q]; }
            sum += __shfl_xor_sync(0xffffffffu, sum, 1);
            sum += __shfl_xor_sync(0xffffffffu, sum, 2);
            float inv = __fdividef(1.f, sum);
            float* op = S + (size_t)row * NN;
#pragma unroll
            for (int nt = 0; nt < 8; ++nt) {
                int c0 = nt * 8 + t2;
                if (c0 < NN)
                    *reinterpret_cast<float2*>(op + c0) =
                        make_float2(v[2 * nt] * inv, v[2 * nt + 1] * inv);
            }
        }
    }
}

// =======================================================================================
// HMMA bf16 GEMM, dual-target (R8-proven config). npass: 1 = ah·bh, 2 = +al·bh, 3 = +ah·bl.
// =======================================================================================
#define MATB 10240u
#define BUFB 40960u

__global__ void __launch_bounds__(256)
gemm_hmma(const __nv_bfloat16* __restrict__ a1hi, const __nv_bfloat16* __restrict__ a1lo,
          int lda1, int k1len,
          const __nv_bfloat16* __restrict__ a2hi, const __nv_bfloat16* __restrict__ a2lo,
          int lda2, int K,
          const __nv_bfloat16* __restrict__ w0hi, const __nv_bfloat16* __restrict__ w0lo,
          const float* __restrict__ b0, float* __restrict__ C0, int act0,
          const __nv_bfloat16* __restrict__ w1hi, const __nv_bfloat16* __restrict__ w1lo,
          const float* __restrict__ b1, float* __restrict__ C1, int act1,
          int nsplit, int npass)
{
    extern __shared__ __align__(16) char dsm[];
    const uint32_t dbase = smem_u32(dsm);

    const int tid = threadIdx.x;
    const int m0 = blockIdx.y * 128;
    const int nb = blockIdx.x;

    const __nv_bfloat16 *whi, *wlo; const float* bias; float* C; int act, nloc;
    if (nb < nsplit) { whi = w0hi; wlo = w0lo; bias = b0; C = C0; act = act0; nloc = nb * 128; }
    else             { whi = w1hi; wlo = w1lo; bias = b1; C = C1; act = act1; nloc = (nb - nsplit) * 128; }

    const int wid = tid >> 5;
    const int lane = tid & 31;
    const int g  = lane >> 2;
    const int t2 = (lane & 3) * 2;
    const int warpM = (wid & 3) * 32;
    const int warpN = (wid >> 2) * 64;

    const int nch = K / 32;

    auto load_chunk = [&](int c) {
        uint32_t sb = dbase + (uint32_t)(c & 1) * BUFB;
        int k0 = c * 32;
        const __nv_bfloat16 *shi, *slo; int ld, kk;
        if (k0 < k1len) { shi = a1hi; slo = a1lo; ld = lda1; kk = k0; }
        else            { shi = a2hi; slo = a2lo; ld = lda2; kk = k0 - k1len; }
#pragma unroll
        for (int i = 0; i < 2; ++i) {
            int gidx = tid + 256 * i;
            int row = gidx >> 2, seg = gidx & 3;
            uint32_t so = (uint32_t)(row * 80 + seg * 16);
            size_t gA = (size_t)(m0 + row) * ld + kk + seg * 8;
            cpasync16(sb + so, shi + gA);
            if (npass >= 2)
                cpasync16(sb + MATB + so, slo + gA);
            size_t gB = (size_t)(nloc + row) * K + k0 + seg * 8;
            cpasync16(sb + 2 * MATB + so, whi + gB);
            if (npass == 3)
                cpasync16(sb + 3 * MATB + so, wlo + gB);
        }
        asm volatile("cp.async.commit_group;" ::: "memory");
    };

    float acc[2][8][4];
#pragma unroll
    for (int mt = 0; mt < 2; ++mt)
#pragma unroll
        for (int nt = 0; nt < 8; ++nt)
#pragma unroll
            for (int q = 0; q < 4; ++q) acc[mt][nt][q] = 0.f;

    load_chunk(0);

    for (int c = 0; c < nch; ++c) {
        if (c + 1 < nch) {
            load_chunk(c + 1);
            asm volatile("cp.async.wait_group 1;" ::: "memory");
        } else {
            asm volatile("cp.async.wait_group 0;" ::: "memory");
        }
        __syncthreads();

        uint32_t sb = dbase + (uint32_t)(c & 1) * BUFB;
#pragma unroll
        for (int ks = 0; ks < 2; ++ks) {
            const uint32_t cb = (uint32_t)((ks * 16 + t2) * 2);
            uint32_t a_h[2][4], a_l[2][4];
#pragma unroll
            for (int mt = 0; mt < 2; ++mt) {
                uint32_t r0 = sb + (uint32_t)((warpM + mt * 16 + g) * 80) + cb;
                uint32_t r8 = r0 + 8 * 80;
                a_h[mt][0] = lds32(r0);        a_h[mt][1] = lds32(r8);
                a_h[mt][2] = lds32(r0 + 16);   a_h[mt][3] = lds32(r8 + 16);
                if (npass >= 2) {
                    a_l[mt][0] = lds32(r0 + MATB); a_l[mt][1] = lds32(r8 + MATB);
                    a_l[mt][2] = lds32(r0 + MATB + 16); a_l[mt][3] = lds32(r8 + MATB + 16);
                }
            }
            uint32_t b_h[8][2];
#pragma unroll
            for (int nt = 0; nt < 8; ++nt) {
                uint32_t rr = sb + 2 * MATB + (uint32_t)((warpN + nt * 8 + g) * 80) + cb;
                b_h[nt][0] = lds32(rr);        b_h[nt][1] = lds32(rr + 16);
            }
            if (npass == 3) {
                uint32_t b_l[8][2];
#pragma unroll
                for (int nt = 0; nt < 8; ++nt) {
                    uint32_t rr = sb + 3 * MATB + (uint32_t)((warpN + nt * 8 + g) * 80) + cb;
                    b_l[nt][0] = lds32(rr);    b_l[nt][1] = lds32(rr + 16);
                }
#pragma unroll
                for (int mt = 0; mt < 2; ++mt)
#pragma unroll
                    for (int nt = 0; nt < 8; ++nt) {
                        mma16816(acc[mt][nt], a_h[mt], b_h[nt]);
                        mma16816(acc[mt][nt], a_h[mt], b_l[nt]);
                        mma16816(acc[mt][nt], a_l[mt], b_h[nt]);
                    }
            } else if (npass == 2) {
#pragma unroll
                for (int mt = 0; mt < 2; ++mt)
#pragma unroll
                    for (int nt = 0; nt < 8; ++nt) {
                        mma16816(acc[mt][nt], a_h[mt], b_h[nt]);
                        mma16816(acc[mt][nt], a_l[mt], b_h[nt]);
                    }
            } else {
#pragma unroll
                for (int mt = 0; mt < 2; ++mt)
#pragma unroll
                    for (int nt = 0; nt < 8; ++nt)
                        mma16816(acc[mt][nt], a_h[mt], b_h[nt]);
            }
        }
        __syncthreads();
    }

#pragma unroll
    for (int mt = 0; mt < 2; ++mt) {
        int r0 = m0 + warpM + mt * 16 + g;
#pragma unroll
        for (int nt = 0; nt < 8; ++nt) {
            int cc = nloc + warpN + nt * 8 + t2;
            float bb0 = bias[cc], bb1 = bias[cc + 1];
            float v0 = acc[mt][nt][0] + bb0, v1 = acc[mt][nt][1] + bb1;
            float v2 = acc[mt][nt][2] + bb0, v3 = acc[mt][nt][3] + bb1;
            if (act == 0) {
                v0 = fast_sigmoid(v0); v1 = fast_sigmoid(v1);
                v2 = fast_sigmoid(v2); v3 = fast_sigmoid(v3);
            } else {
                v0 = fast_tanh(v0); v1 = fast_tanh(v1);
                v2 = fast_tanh(v2); v3 = fast_tanh(v3);
            }
            *reinterpret_cast<float2*>(&C[(size_t)r0 * 256 + cc])       = make_float2(v0, v1);
            *reinterpret_cast<float2*>(&C[(size_t)(r0 + 8) * 256 + cc]) = make_float2(v2, v3);
        }
    }
}

// =======================================================================================
// Scan, warp-autonomous (R8-proven, unchanged).
// =======================================================================================
__global__ void __launch_bounds__(256) scan_kernel(const float* __restrict__ S,
                                                   const float* __restrict__ E,
                                                   const float* __restrict__ A,
                                                   const float* __restrict__ M0,
                                                   __nv_bfloat16* __restrict__ Rhi,
                                                   __nv_bfloat16* __restrict__ Rlo)
{
    const int b = blockIdx.x;
    const int d = threadIdx.x;
    const int w = d >> 5;
    const int lane = d & 31;
    __shared__ __align__(16) float ring[8][16][52];

    u64 m[25];
#pragma unroll
    for (int j = 0; j < 25; ++j)
        m[j] = pack2(M0[(2 * j) * DV + d], M0[(2 * j + 1) * DV + d]);

    const float* sp = S + (size_t)b * LL * NN;
    const float* ep = E + (size_t)b * LL * DV + d;
    const float* ap = A + (size_t)b * LL * DV + d;
    __nv_bfloat16* rh = Rhi + (size_t)b * LL * DV + d;
    __nv_bfloat16* rl = Rlo + (size_t)b * LL * DV + d;

    auto fetch_slot = [&](int slot, int l) {
        if (lane < 25)
            cpasync8(smem_u32(&ring[w][slot][lane * 2]), sp + (size_t)l * NN + lane * 2);
    };

#pragma unroll
    for (int st = 0; st < 4; ++st) fetch_slot(st, st);
    asm volatile("cp.async.commit_group;" ::: "memory");
#pragma unroll
    for (int st = 0; st < 4; ++st) fetch_slot(4 + st, 4 + st);
    asm volatile("cp.async.commit_group;" ::: "memory");
    asm volatile("cp.async.wait_group 1;" ::: "memory");

    float ecur[4], acur[4], enx[4], anx[4];
#pragma unroll
    for (int st = 0; st < 4; ++st) { ecur[st] = ep[(size_t)st * DV]; acur[st] = ap[(size_t)st * DV]; }
#pragma unroll
    for (int st = 0; st < 4; ++st) { enx[st] = ep[(size_t)(4 + st) * DV]; anx[st] = ap[(size_t)(4 + st) * DV]; }
    __syncwarp();

    for (int gi = 0; gi < LL / 4; ++gi) {
        const int base = gi * 4;
#pragma unroll
        for (int st = 0; st < 4; ++st) {
            int ll = base + 8 + st; if (ll > LL - 1) ll = LL - 1;
            fetch_slot((base + 8 + st) & 15, ll);
        }
        asm volatile("cp.async.commit_group;" ::: "memory");
        float etmp[4], atmp[4];
#pragma unroll
        for (int st = 0; st < 4; ++st) {
            int ll = base + 8 + st; if (ll > LL - 1) ll = LL - 1;
            etmp[st] = ep[(size_t)ll * DV];
            atmp[st] = ap[(size_t)ll * DV];
        }

#pragma unroll
        for (int st = 0; st < 4; ++st) {
            const int l = base + st;
            u64 apk  = pack2(acur[st], acur[st]);
            u64 nepk = pack2(-ecur[st], -ecur[st]);
            u64 r0 = 0ull, r1 = 0ull;
            const u64* sb = reinterpret_cast<const u64*>(ring[w][l & 15]);
#pragma unroll
            for (int j = 0; j < 25; ++j) {
                u64 spk = sb[j];
                if (j & 1) r1 = fma2(spk, m[j], r1);
                else       r0 = fma2(spk, m[j], r0);
                u64 tt = fma2(nepk, m[j], apk);
                m[j] = fma2(spk, tt, m[j]);
            }
            float2 rv = unpack2(add2(r0, r1));
            float rr = rv.x + rv.y;
            __nv_bfloat16 h  = __float2bfloat16(rr);
            __nv_bfloat16 lo = __float2bfloat16(rr - __bfloat162float(h));
            rh[(size_t)l * DV] = h;
            rl[(size_t)l * DV] = lo;
        }

        asm volatile("cp.async.wait_group 1;" ::: "memory");
        __syncwarp();
#pragma unroll
        for (int st = 0; st < 4; ++st) {
            ecur[st] = enx[st]; acur[st] = anx[st];
            enx[st] = etmp[st]; anx[st] = atmp[st];
        }
    }
}

// =======================================================================================
// Launch — stream-forked DAG: side stream runs {conv_p, conv_w, score} concurrently
// with {conv_ib, gate GEMMs}; join before scan. Event edges are graph-capturable.
// =======================================================================================
extern "C" void kernel_launch(void* const* d_in, const int* in_sizes, int n_in,
                              void* d_out, int out_size)
{
    const float* problems     = (const float*)d_in[0];
    const float* interactions = (const float*)d_in[1];
    const float* w_key        = (const float*)d_in[2];
    const float* w_erase_w    = (const float*)d_in[3];
    const float* w_erase_b    = (const float*)d_in[4];
    const float* w_add_w      = (const float*)d_in[5];
    const float* w_add_b      = (const float*)d_in[6];
    const float* w_out_w      = (const float*)d_in[7];
    const float* w_out_b      = (const float*)d_in[8];
    const float* init_memory  = (const float*)d_in[9];
    float* out = (float*)d_out;

    float *ge, *ga, *gs;
    __nv_bfloat16 *ibhi, *pbhi, *pblo, *rhi, *rlo;
    __nv_bfloat16 *wehi, *wahi, *wohi, *wolo, *wkhi, *wklo;
    cudaGetSymbolAddress((void**)&ge,   g_e);
    cudaGetSymbolAddress((void**)&ga,   g_a);
    cudaGetSymbolAddress((void**)&gs,   g_score);
    cudaGetSymbolAddress((void**)&ibhi, g_ibhi);
    cudaGetSymbolAddress((void**)&pbhi, g_pbhi);  cudaGetSymbolAddress((void**)&pblo, g_pblo);
    cudaGetSymbolAddress((void**)&rhi,  g_rhi);   cudaGetSymbolAddress((void**)&rlo,  g_rlo);
    cudaGetSymbolAddress((void**)&wehi, g_wehi);
    cudaGetSymbolAddress((void**)&wahi, g_wahi);
    cudaGetSymbolAddress((void**)&wohi, g_wohi);  cudaGetSymbolAddress((void**)&wolo, g_wolo);
    cudaGetSymbolAddress((void**)&wkhi, g_wkhi);  cudaGetSymbolAddress((void**)&wklo, g_wklo);

    cudaFuncSetAttribute(gemm_hmma, cudaFuncAttributeMaxDynamicSharedMemorySize, 2 * BUFB);
    cudaFuncSetAttribute(score_hmma, cudaFuncAttributeMaxDynamicSharedMemorySize, 2 * SBUF);

    // persistent side stream + events (created on first, non-captured, call)
    static cudaStream_t s2 = nullptr;
    static cudaEvent_t ev_fork = nullptr, ev_join = nullptr;
    if (!s2) {
        cudaStreamCreateWithFlags(&s2, cudaStreamNonBlocking);
        cudaEventCreateWithFlags(&ev_fork, cudaEventDisableTiming);
        cudaEventCreateWithFlags(&ev_join, cudaEventDisableTiming);
    }

    // fork
    cudaEventRecord(ev_fork, 0);
    cudaStreamWaitEvent(s2, ev_fork, 0);

    // ---- side stream: problems conv + weight conv + score ----
    conv_kernel<<<(MM * DK / 4 + 255) / 256, 256, 0, s2>>>(problems, pbhi, pblo, MM * DK / 4);
    {
        int n0 = DV * DV / 4, n1 = DV * DV / 4, n2 = HH * (DV + DK) / 4, n3 = NN * DK / 4;
        int nt = n0 + n1 + n2 + n3;
        conv_w_kernel<<<(nt + 255) / 256, 256, 0, s2>>>(w_erase_w, wehi, n0,
                                                        w_add_w,   wahi, n1,
                                                        w_out_w,   wohi, wolo, n2,
                                                        w_key,     wkhi, wklo, n3);
    }
    score_hmma<<<MM / 128, 128, 2 * SBUF, s2>>>(pbhi, pblo, wkhi, wklo, gs);
    cudaEventRecord(ev_join, s2);

    // ---- main stream: interactions conv + gate GEMMs ----
    conv_hi_kernel<<<(MM * DV / 4 + 255) / 256, 256>>>(interactions, ibhi, MM * DV / 4);
    dim3 gg(4, MM / 128);
    gemm_hmma<<<gg, 256, 2 * BUFB>>>(ibhi, ibhi, DV, DV, ibhi, ibhi, DV, DV,
                                     wehi, wehi, w_erase_b, ge, /*sigmoid*/0,
                                     wahi, wahi, w_add_b,   ga, /*tanh*/1, 2, /*npass*/1);

    // join: scan needs score (s2) + gates (main)
    cudaStreamWaitEvent(0, ev_join, 0);

    // sequential memory scan (warp-autonomous)
    scan_kernel<<<BB, 256>>>(gs, ge, ga, init_memory, rhi, rlo);

    // output GEMM — 3-pass (writes graded output)
    dim3 go(2, MM / 128);
    gemm_hmma<<<go, 256, 2 * BUFB>>>(rhi, rlo, DV, DV, pbhi, pblo, DK, DV + DK,
                                     wohi, wolo, w_out_b, out, /*tanh*/1,
                                     wohi, wolo, w_out_b, out, 1, 2, /*npass*/3);
}